// round 9
// baseline (speedup 1.0000x reference)
#include <cuda_runtime.h>
#include <cuda_bf16.h>
#include <cstdint>

// ---------------------------------------------------------------------------
// Instant-NGP MLP via mma.sync m16n8k16 BF16, split-bf16 (3-term).
// Round 9: static tile schedule, software-pipelined gather (corner LDGs for
// tile t+148 in flight across GEMM2 of tile t), feat double-buffered,
// 3 barriers/tile.
// ---------------------------------------------------------------------------

#define NPTS    2097152
#define NTILES  (NPTS / 128)     // 16384
#define TPB     512
#define NCTA    148
#define GS      513

// SMEM map in u32 units
#define U_W1FH  0                 // 2048
#define U_W1FL  2048
#define U_W2FH  4096              // 8192
#define U_W2FL  12288
#define U_FEAT  20480             // 2 bufs x (H 2560 + L 2560) = 10240
#define FEAT_PL 2560
#define U_H1H   30720             // 128*68 = 8704
#define U_H1L   39424
#define F_B1    48128
#define F_B2    48256
#define F_W3    48384
#define F_B3    48512             // 4
#define F_PART  48516             // 256
#define SM_U32  48772
#define SMEM_BYTES (SM_U32 * 4)   // 195088 B

__device__ constexpr int kResTab[16] = {16, 20, 25, 32, 40, 50, 64, 80,
                                        101, 128, 161, 203, 256, 322, 406, 512};

__device__ __forceinline__ float bf16f(float v) {
    return __bfloat162float(__float2bfloat16_rn(v));
}
__device__ __forceinline__ uint32_t packbf(float e0, float e1) {
    __nv_bfloat162 t = __halves2bfloat162(__float2bfloat16_rn(e0),
                                          __float2bfloat16_rn(e1));
    return *reinterpret_cast<uint32_t*>(&t);
}

__device__ __forceinline__ void mmab(float* d, const uint32_t* a,
                                     uint32_t b0, uint32_t b1) {
    asm volatile(
        "mma.sync.aligned.m16n8k16.row.col.f32.bf16.bf16.f32 "
        "{%0,%1,%2,%3}, {%4,%5,%6,%7}, {%8,%9}, {%0,%1,%2,%3};"
        : "+f"(d[0]), "+f"(d[1]), "+f"(d[2]), "+f"(d[3])
        : "r"(a[0]), "r"(a[1]), "r"(a[2]), "r"(a[3]), "r"(b0), "r"(b1));
}

// pinned-issue-point global load (keeps prefetch LDGs before the barrier)
__device__ __forceinline__ float2 ldg2(const float2* p) {
    float2 v;
    asm volatile("ld.global.nc.v2.f32 {%0,%1}, [%2];"
                 : "=f"(v.x), "=f"(v.y) : "l"(p));
    return v;
}

// ---- pipelined gather phases (4 levels per thread, compile-time base) ----
template <int L0>
__device__ __forceinline__ void gissue(float2 xy, const float* __restrict__ grids,
                                       float2* c) {
    #pragma unroll
    for (int i = 0; i < 4; i++) {
        const int   ri = kResTab[L0 + i];
        const float rf = (float)ri;
        int ix0 = min(max((int)floorf(xy.x * rf), 0), ri);
        int iy0 = min(max((int)floorf(xy.y * rf), 0), ri);
        int ix1 = min(ix0 + 1, ri);
        int iy1 = min(iy0 + 1, ri);
        const float2* g = reinterpret_cast<const float2*>(grids)
                        + (size_t)(L0 + i) * (GS * GS);
        c[4*i+0] = ldg2(g + ix0 * GS + iy0);
        c[4*i+1] = ldg2(g + ix1 * GS + iy0);
        c[4*i+2] = ldg2(g + ix0 * GS + iy1);
        c[4*i+3] = ldg2(g + ix1 * GS + iy1);
    }
}
template <int L0>
__device__ __forceinline__ void gxlerp(float2 xy, const float2* c, float4* ab) {
    #pragma unroll
    for (int i = 0; i < 4; i++) {
        const float rf = (float)kResTab[L0 + i];
        const float fx = xy.x * rf;
        const float wx = fx - floorf(fx), owx = 1.0f - wx;
        ab[i].x = c[4*i+0].x * owx + c[4*i+1].x * wx;
        ab[i].y = c[4*i+0].y * owx + c[4*i+1].y * wx;
        ab[i].z = c[4*i+2].x * owx + c[4*i+3].x * wx;
        ab[i].w = c[4*i+2].y * owx + c[4*i+3].y * wx;
    }
}
template <int L0>
__device__ __forceinline__ void gylerp(float2 xy, const float4* ab, float* f) {
    #pragma unroll
    for (int i = 0; i < 4; i++) {
        const float rf = (float)kResTab[L0 + i];
        const float fy = xy.y * rf;
        const float wy = fy - floorf(fy), owy = 1.0f - wy;
        f[2*i+0] = ab[i].x * owy + ab[i].z * wy;
        f[2*i+1] = ab[i].y * owy + ab[i].w * wy;
    }
}

__global__ __launch_bounds__(TPB, 1)
void Model_61065845014888_kernel(
    const float* __restrict__ x,
    const float* __restrict__ grids,
    const float* __restrict__ W1, const float* __restrict__ b1,
    const float* __restrict__ W2, const float* __restrict__ b2,
    const float* __restrict__ W3, const float* __restrict__ b3,
    float* __restrict__ out)
{
    extern __shared__ float sm[];
    uint32_t* smu = reinterpret_cast<uint32_t*>(sm);
    const int tid = threadIdx.x;

    // ---- stage split-bf16 weight fragments, once ----
    for (int i = tid; i < 2048; i += TPB) {
        int r = i & 1, ln = (i >> 1) & 31, g = (i >> 6) & 15, s = i >> 10;
        int k = s * 16 + 2 * (ln & 3) + 8 * r;
        int j = g * 8 + (ln >> 2);
        float w0 = W1[k * 128 + j], w1 = W1[(k + 1) * 128 + j];
        float h0 = bf16f(w0), h1 = bf16f(w1);
        smu[U_W1FH + i] = packbf(h0, h1);
        smu[U_W1FL + i] = packbf(w0 - h0, w1 - h1);
    }
    for (int i = tid; i < 8192; i += TPB) {
        int r = i & 1, ln = (i >> 1) & 31, g = (i >> 6) & 15, s = i >> 10;
        int k = s * 16 + 2 * (ln & 3) + 8 * r;
        int j = g * 8 + (ln >> 2);
        float w0 = W2[k * 128 + j], w1 = W2[(k + 1) * 128 + j];
        float h0 = bf16f(w0), h1 = bf16f(w1);
        smu[U_W2FH + i] = packbf(h0, h1);
        smu[U_W2FL + i] = packbf(w0 - h0, w1 - h1);
    }
    if (tid < 128) {
        sm[F_B1 + tid] = b1[tid];
        sm[F_B2 + tid] = b2[tid];
        sm[F_W3 + tid] = W3[tid];
    }
    if (tid == 0) sm[F_B3] = b3[0];

    const int wid  = tid >> 5;
    const int lane = tid & 31;
    const int rg   = wid & 7;
    const int ch   = wid >> 3;
    const int tg   = lane & 3;
    const int gid  = lane >> 2;
    const int arow = rg * 16 + gid;
    const int jw   = ch * 64;

    const int gpt = tid >> 2;
    const int gq  = tid & 3;

    // ---- prologue: gather tile blockIdx.x into feat buf 0 ----
    {
        const int p = blockIdx.x * 128 + gpt;
        const float2 xy = __ldg(reinterpret_cast<const float2*>(x) + p);
        float2 c[16]; float4 ab[4]; float f[8];
        switch (gq) {
            case 0: gissue<0>(xy, grids, c);  gxlerp<0>(xy, c, ab);  gylerp<0>(xy, ab, f);  break;
            case 1: gissue<4>(xy, grids, c);  gxlerp<4>(xy, c, ab);  gylerp<4>(xy, ab, f);  break;
            case 2: gissue<8>(xy, grids, c);  gxlerp<8>(xy, c, ab);  gylerp<8>(xy, ab, f);  break;
            default: gissue<12>(xy, grids, c); gxlerp<12>(xy, c, ab); gylerp<12>(xy, ab, f); break;
        }
        uint32_t hi[4], lo[4];
        #pragma unroll
        for (int cc = 0; cc < 4; cc++) {
            float h0 = bf16f(f[2*cc]), h1 = bf16f(f[2*cc+1]);
            hi[cc] = packbf(h0, h1);
            lo[cc] = packbf(f[2*cc] - h0, f[2*cc+1] - h1);
        }
        *reinterpret_cast<uint4*>(smu + U_FEAT + gpt * 20 + gq * 4) =
            make_uint4(hi[0], hi[1], hi[2], hi[3]);
        *reinterpret_cast<uint4*>(smu + U_FEAT + FEAT_PL + gpt * 20 + gq * 4) =
            make_uint4(lo[0], lo[1], lo[2], lo[3]);
    }

    int buf = 0;
    for (int t = blockIdx.x; t < NTILES; t += NCTA, buf ^= 1) {
        // prefetch next tile's xy early (1 LDG, consumed ~2k cyc later)
        const int  tn      = t + NCTA;
        const bool hasnext = tn < NTILES;
        const int  pn      = (hasnext ? tn : t) * 128 + gpt;
        const float2 xyn   = __ldg(reinterpret_cast<const float2*>(x) + pn);

        __syncthreads();   // feat[buf] visible, h1 free

        const int fbH = U_FEAT + buf * (2 * FEAT_PL);
        const int fbL = fbH + FEAT_PL;

        float d[8][4];

        // ============ GEMM1: D1 = feat @ W1 + b1 (2 k16-steps) ============
        #pragma unroll
        for (int f = 0; f < 8; f++) {
            const float2 bv = *reinterpret_cast<const float2*>(
                sm + F_B1 + jw + f * 8 + tg * 2);
            d[f][0] = bv.x; d[f][1] = bv.y;
            d[f][2] = bv.x; d[f][3] = bv.y;
        }
        #pragma unroll
        for (int s = 0; s < 2; s++) {
            const int acol = s * 8 + tg;
            uint32_t ah[4], al[4];
            ah[0] = smu[fbH + arow * 20 + acol];
            ah[1] = smu[fbH + (arow + 8) * 20 + acol];
            ah[2] = smu[fbH + arow * 20 + acol + 4];
            ah[3] = smu[fbH + (arow + 8) * 20 + acol + 4];
            al[0] = smu[fbL + arow * 20 + acol];
            al[1] = smu[fbL + (arow + 8) * 20 + acol];
            al[2] = smu[fbL + arow * 20 + acol + 4];
            al[3] = smu[fbL + (arow + 8) * 20 + acol + 4];
            const int fb = ((s * 16 + ch * 8) * 32 + lane) * 2;
            #pragma unroll
            for (int f = 0; f < 8; f++) {
                const uint2 wh = *reinterpret_cast<const uint2*>(
                    smu + U_W1FH + fb + f * 64);
                const uint2 wl = *reinterpret_cast<const uint2*>(
                    smu + U_W1FL + fb + f * 64);
                mmab(d[f], ah, wh.x, wh.y);
                mmab(d[f], al, wh.x, wh.y);
                mmab(d[f], ah, wl.x, wl.y);
            }
        }

        // relu + split-store h1
        #pragma unroll
        for (int f = 0; f < 8; f++) {
            const int jc = jw / 2 + f * 4 + tg;
            float v0 = fmaxf(d[f][0], 0.0f), v1 = fmaxf(d[f][1], 0.0f);
            float v2 = fmaxf(d[f][2], 0.0f), v3 = fmaxf(d[f][3], 0.0f);
            float h0 = bf16f(v0), h1 = bf16f(v1), h2 = bf16f(v2), h3 = bf16f(v3);
            smu[U_H1H + arow * 68 + jc]       = packbf(h0, h1);
            smu[U_H1L + arow * 68 + jc]       = packbf(v0 - h0, v1 - h1);
            smu[U_H1H + (arow + 8) * 68 + jc] = packbf(h2, h3);
            smu[U_H1L + (arow + 8) * 68 + jc] = packbf(v2 - h2, v3 - h3);
        }

        // ---- issue next-tile gather LDGs (latency hidden by GEMM2) ----
        float2 c[16];
        switch (gq) {
            case 0: gissue<0>(xyn, grids, c);  break;
            case 1: gissue<4>(xyn, grids, c);  break;
            case 2: gissue<8>(xyn, grids, c);  break;
            default: gissue<12>(xyn, grids, c); break;
        }

        __syncthreads();   // h1 visible

        // ============ GEMM2: D2 = h1 @ W2 + b2 (8 k16-steps) ============
        #pragma unroll
        for (int f = 0; f < 8; f++) {
            const float2 bv = *reinterpret_cast<const float2*>(
                sm + F_B2 + jw + f * 8 + tg * 2);
            d[f][0] = bv.x; d[f][1] = bv.y;
            d[f][2] = bv.x; d[f][3] = bv.y;
        }
        float4 ab[4];
        #pragma unroll 1
        for (int s = 0; s < 8; s++) {
            const int acol = s * 8 + tg;
            uint32_t ah[4], al[4];
            ah[0] = smu[U_H1H + arow * 68 + acol];
            ah[1] = smu[U_H1H + (arow + 8) * 68 + acol];
            ah[2] = smu[U_H1H + arow * 68 + acol + 4];
            ah[3] = smu[U_H1H + (arow + 8) * 68 + acol + 4];
            al[0] = smu[U_H1L + arow * 68 + acol];
            al[1] = smu[U_H1L + (arow + 8) * 68 + acol];
            al[2] = smu[U_H1L + arow * 68 + acol + 4];
            al[3] = smu[U_H1L + (arow + 8) * 68 + acol + 4];
            const int fb = ((s * 16 + ch * 8) * 32 + lane) * 2;
            #pragma unroll
            for (int f = 0; f < 8; f++) {
                const uint2 wh = *reinterpret_cast<const uint2*>(
                    smu + U_W2FH + fb + f * 64);
                const uint2 wl = *reinterpret_cast<const uint2*>(
                    smu + U_W2FL + fb + f * 64);
                mmab(d[f], ah, wh.x, wh.y);
                mmab(d[f], al, wh.x, wh.y);
                mmab(d[f], ah, wl.x, wl.y);
            }
            if (s == 3) {
                // corners have landed; shrink held gather state 32->16 floats
                switch (gq) {
                    case 0: gxlerp<0>(xyn, c, ab);  break;
                    case 1: gxlerp<4>(xyn, c, ab);  break;
                    case 2: gxlerp<8>(xyn, c, ab);  break;
                    default: gxlerp<12>(xyn, c, ab); break;
                }
            }
        }

        // ============ epilogue: relu + W3 dot + reduce ============
        {
            float slo = 0.0f, shi = 0.0f;
            #pragma unroll
            for (int f = 0; f < 8; f++) {
                const int jc = jw + f * 8 + tg * 2;
                const float w3a = sm[F_W3 + jc];
                const float w3b = sm[F_W3 + jc + 1];
                slo = fmaf(fmaxf(d[f][0], 0.0f), w3a, slo);
                slo = fmaf(fmaxf(d[f][1], 0.0f), w3b, slo);
                shi = fmaf(fmaxf(d[f][2], 0.0f), w3a, shi);
                shi = fmaf(fmaxf(d[f][3], 0.0f), w3b, shi);
            }
            slo += __shfl_xor_sync(0xFFFFFFFF, slo, 1);
            slo += __shfl_xor_sync(0xFFFFFFFF, slo, 2);
            shi += __shfl_xor_sync(0xFFFFFFFF, shi, 1);
            shi += __shfl_xor_sync(0xFFFFFFFF, shi, 2);
            if (tg == 0) {
                sm[F_PART + arow * 2 + ch]       = slo;
                sm[F_PART + (arow + 8) * 2 + ch] = shi;
            }
        }
        __syncthreads();   // PART visible

        if (tid < 128)
            out[t * 128 + tid] = sm[F_PART + tid * 2]
                               + sm[F_PART + tid * 2 + 1]
                               + sm[F_B3];

        // ---- finish pipelined gather: y-lerp + split -> feat[buf^1] ----
        if (hasnext) {
            float f[8];
            switch (gq) {
                case 0: gylerp<0>(xyn, ab, f);  break;
                case 1: gylerp<4>(xyn, ab, f);  break;
                case 2: gylerp<8>(xyn, ab, f);  break;
                default: gylerp<12>(xyn, ab, f); break;
            }
            uint32_t hi[4], lo[4];
            #pragma unroll
            for (int cc = 0; cc < 4; cc++) {
                float h0 = bf16f(f[2*cc]), h1 = bf16f(f[2*cc+1]);
                hi[cc] = packbf(h0, h1);
                lo[cc] = packbf(f[2*cc] - h0, f[2*cc+1] - h1);
            }
            const int nbH = U_FEAT + (buf ^ 1) * (2 * FEAT_PL);
            *reinterpret_cast<uint4*>(smu + nbH + gpt * 20 + gq * 4) =
                make_uint4(hi[0], hi[1], hi[2], hi[3]);
            *reinterpret_cast<uint4*>(smu + nbH + FEAT_PL + gpt * 20 + gq * 4) =
                make_uint4(lo[0], lo[1], lo[2], lo[3]);
        }
        // visibility provided by next iteration's top barrier
    }
}

extern "C" void kernel_launch(void* const* d_in, const int* in_sizes, int n_in,
                              void* d_out, int out_size)
{
    const float* x     = (const float*)d_in[0];
    const float* grids = (const float*)d_in[1];
    const float* W1    = (const float*)d_in[2];
    const float* b1    = (const float*)d_in[3];
    const float* W2    = (const float*)d_in[4];
    const float* b2    = (const float*)d_in[5];
    const float* W3    = (const float*)d_in[6];
    const float* b3    = (const float*)d_in[7];
    float* out = (float*)d_out;
    (void)in_sizes; (void)n_in; (void)out_size;

    cudaFuncSetAttribute(Model_61065845014888_kernel,
                         cudaFuncAttributeMaxDynamicSharedMemorySize, SMEM_BYTES);

    Model_61065845014888_kernel<<<NCTA, TPB, SMEM_BYTES>>>(
        x, grids, W1, b1, W2, b2, W3, b3, out);
}

// round 10
// speedup vs baseline: 1.2329x; 1.2329x over previous
#include <cuda_runtime.h>
#include <cuda_bf16.h>
#include <cstdint>

// ---------------------------------------------------------------------------
// Instant-NGP MLP via mma.sync m16n8k16 BF16, split-bf16 (3-term).
// Round 10: grid repacked once per launch into y-pair float4 ->
// 2 LDG.128 per level (32 LDG/point, was 64). Round-8 GEMM structure,
// static tile schedule, 3 barriers/tile.
// ---------------------------------------------------------------------------

#define NPTS    2097152
#define NTILES  (NPTS / 128)     // 16384
#define TPB     512
#define NCTA    148
#define GS      513
#define GC      (GS * GS)

// SMEM map in u32 units
#define U_W1FH  0                 // 2048
#define U_W1FL  2048
#define U_W2FH  4096              // 8192
#define U_W2FL  12288
#define U_FEATH 20480             // 128*20 = 2560
#define U_FEATL 23040
#define U_H1H   25600             // 128*68 = 8704
#define U_H1L   34304
#define F_B1    43008
#define F_B2    43136
#define F_W3    43264
#define F_B3    43392             // 4
#define F_PART  43396             // 256
#define SM_U32  43652
#define SMEM_BYTES (SM_U32 * 4)   // 174608 B

// y-pair packed grid: P[l][i][j] = (g[i][j].xy, g[i][j+1].xy)
__device__ float4 g_pack[16 * GC];   // 67.4 MB scratch (device global)

__device__ constexpr int kResTab[16] = {16, 20, 25, 32, 40, 50, 64, 80,
                                        101, 128, 161, 203, 256, 322, 406, 512};

__device__ __forceinline__ float bf16f(float v) {
    return __bfloat162float(__float2bfloat16_rn(v));
}
__device__ __forceinline__ uint32_t packbf(float e0, float e1) {
    __nv_bfloat162 t = __halves2bfloat162(__float2bfloat16_rn(e0),
                                          __float2bfloat16_rn(e1));
    return *reinterpret_cast<uint32_t*>(&t);
}

__device__ __forceinline__ void mmab(float* d, const uint32_t* a,
                                     uint32_t b0, uint32_t b1) {
    asm volatile(
        "mma.sync.aligned.m16n8k16.row.col.f32.bf16.bf16.f32 "
        "{%0,%1,%2,%3}, {%4,%5,%6,%7}, {%8,%9}, {%0,%1,%2,%3};"
        : "+f"(d[0]), "+f"(d[1]), "+f"(d[2]), "+f"(d[3])
        : "r"(a[0]), "r"(a[1]), "r"(a[2]), "r"(a[3]), "r"(b0), "r"(b1));
}

// grid repack: 2 float2 reads -> 1 aligned float4 (y-pair)
__global__ __launch_bounds__(256)
void repack_kernel(const float* __restrict__ grids) {
    int idx = blockIdx.x * 256 + threadIdx.x;
    if (idx >= 16 * GC) return;
    int j = idx % GS;
    int i = (idx / GS) % GS;
    int l = idx / GC;
    const float2* g = reinterpret_cast<const float2*>(grids) + (size_t)l * GC;
    float2 a = __ldg(g + i * GS + j);
    float2 b = __ldg(g + i * GS + min(j + 1, GS - 1));
    g_pack[idx] = make_float4(a.x, a.y, b.x, b.y);
}

// 4-level gather via packed grid: 2 LDG.128 per level
template <int L0>
__device__ __forceinline__ void gather4(float2 xy, float* f) {
    #pragma unroll
    for (int i = 0; i < 4; i++) {
        const int   ri = kResTab[L0 + i];
        const float rf = (float)ri;
        const float fx = xy.x * rf, fy = xy.y * rf;
        const float fxf = floorf(fx), fyf = floorf(fy);
        const float wx = fx - fxf, wy = fy - fyf;
        int ix0 = min(max((int)fxf, 0), ri);
        int iy0 = min(max((int)fyf, 0), ri);
        int ix1 = min(ix0 + 1, ri);
        const float4* P = g_pack + (size_t)(L0 + i) * GC;
        const float4 a = __ldg(P + ix0 * GS + iy0);   // f00, f01
        const float4 b = __ldg(P + ix1 * GS + iy0);   // f10, f11
        const float owx = 1.0f - wx, owy = 1.0f - wy;
        const float t00 = a.x * owx + b.x * wx;
        const float t01 = a.y * owx + b.y * wx;
        const float t10 = a.z * owx + b.z * wx;
        const float t11 = a.w * owx + b.w * wx;
        f[2 * i + 0] = t00 * owy + t10 * wy;
        f[2 * i + 1] = t01 * owy + t11 * wy;
    }
}

__global__ __launch_bounds__(TPB, 1)
void Model_61065845014888_kernel(
    const float* __restrict__ x,
    const float* __restrict__ W1, const float* __restrict__ b1,
    const float* __restrict__ W2, const float* __restrict__ b2,
    const float* __restrict__ W3, const float* __restrict__ b3,
    float* __restrict__ out)
{
    extern __shared__ float sm[];
    uint32_t* smu = reinterpret_cast<uint32_t*>(sm);
    const int tid = threadIdx.x;

    // ---- stage split-bf16 weight fragments, once ----
    for (int i = tid; i < 2048; i += TPB) {
        int r = i & 1, ln = (i >> 1) & 31, g = (i >> 6) & 15, s = i >> 10;
        int k = s * 16 + 2 * (ln & 3) + 8 * r;
        int j = g * 8 + (ln >> 2);
        float w0 = W1[k * 128 + j], w1 = W1[(k + 1) * 128 + j];
        float h0 = bf16f(w0), h1 = bf16f(w1);
        smu[U_W1FH + i] = packbf(h0, h1);
        smu[U_W1FL + i] = packbf(w0 - h0, w1 - h1);
    }
    for (int i = tid; i < 8192; i += TPB) {
        int r = i & 1, ln = (i >> 1) & 31, g = (i >> 6) & 15, s = i >> 10;
        int k = s * 16 + 2 * (ln & 3) + 8 * r;
        int j = g * 8 + (ln >> 2);
        float w0 = W2[k * 128 + j], w1 = W2[(k + 1) * 128 + j];
        float h0 = bf16f(w0), h1 = bf16f(w1);
        smu[U_W2FH + i] = packbf(h0, h1);
        smu[U_W2FL + i] = packbf(w0 - h0, w1 - h1);
    }
    if (tid < 128) {
        sm[F_B1 + tid] = b1[tid];
        sm[F_B2 + tid] = b2[tid];
        sm[F_W3 + tid] = W3[tid];
    }
    if (tid == 0) sm[F_B3] = b3[0];

    const int wid  = tid >> 5;
    const int lane = tid & 31;
    const int rg   = wid & 7;
    const int ch   = wid >> 3;
    const int tg   = lane & 3;
    const int gid  = lane >> 2;
    const int arow = rg * 16 + gid;
    const int jw   = ch * 64;

    const int gpt = tid >> 2;
    const int gq  = tid & 3;

    __syncthreads();

    for (int t = blockIdx.x; t < NTILES; t += NCTA) {
        // ============ gather -> split bf16 feat (stride 20 u32) ============
        {
            const int p = t * 128 + gpt;
            const float2 xy = __ldg(reinterpret_cast<const float2*>(x) + p);
            float f[8];
            switch (gq) {
                case 0: gather4<0>(xy, f);  break;
                case 1: gather4<4>(xy, f);  break;
                case 2: gather4<8>(xy, f);  break;
                default: gather4<12>(xy, f); break;
            }
            uint32_t hi[4], lo[4];
            #pragma unroll
            for (int c = 0; c < 4; c++) {
                float h0 = bf16f(f[2*c]), h1 = bf16f(f[2*c+1]);
                hi[c] = packbf(h0, h1);
                lo[c] = packbf(f[2*c] - h0, f[2*c+1] - h1);
            }
            *reinterpret_cast<uint4*>(smu + U_FEATH + gpt * 20 + gq * 4) =
                make_uint4(hi[0], hi[1], hi[2], hi[3]);
            *reinterpret_cast<uint4*>(smu + U_FEATL + gpt * 20 + gq * 4) =
                make_uint4(lo[0], lo[1], lo[2], lo[3]);
        }
        __syncthreads();

        float d[8][4];

        // ============ GEMM1: D1 = feat @ W1 + b1 (2 k16-steps) ============
        #pragma unroll
        for (int f = 0; f < 8; f++) {
            const float2 bv = *reinterpret_cast<const float2*>(
                sm + F_B1 + jw + f * 8 + tg * 2);
            d[f][0] = bv.x; d[f][1] = bv.y;
            d[f][2] = bv.x; d[f][3] = bv.y;
        }
        #pragma unroll
        for (int s = 0; s < 2; s++) {
            const int acol = s * 8 + tg;
            uint32_t ah[4], al[4];
            ah[0] = smu[U_FEATH + arow * 20 + acol];
            ah[1] = smu[U_FEATH + (arow + 8) * 20 + acol];
            ah[2] = smu[U_FEATH + arow * 20 + acol + 4];
            ah[3] = smu[U_FEATH + (arow + 8) * 20 + acol + 4];
            al[0] = smu[U_FEATL + arow * 20 + acol];
            al[1] = smu[U_FEATL + (arow + 8) * 20 + acol];
            al[2] = smu[U_FEATL + arow * 20 + acol + 4];
            al[3] = smu[U_FEATL + (arow + 8) * 20 + acol + 4];
            const int fb = ((s * 16 + ch * 8) * 32 + lane) * 2;
            #pragma unroll
            for (int f = 0; f < 8; f++) {
                const uint2 wh = *reinterpret_cast<const uint2*>(
                    smu + U_W1FH + fb + f * 64);
                const uint2 wl = *reinterpret_cast<const uint2*>(
                    smu + U_W1FL + fb + f * 64);
                mmab(d[f], ah, wh.x, wh.y);
                mmab(d[f], al, wh.x, wh.y);
                mmab(d[f], ah, wl.x, wl.y);
            }
        }

        // relu + split-store h1 (stride 68 u32)
        #pragma unroll
        for (int f = 0; f < 8; f++) {
            const int jc = jw / 2 + f * 4 + tg;
            float v0 = fmaxf(d[f][0], 0.0f), v1 = fmaxf(d[f][1], 0.0f);
            float v2 = fmaxf(d[f][2], 0.0f), v3 = fmaxf(d[f][3], 0.0f);
            float h0 = bf16f(v0), h1 = bf16f(v1), h2 = bf16f(v2), h3 = bf16f(v3);
            smu[U_H1H + arow * 68 + jc]       = packbf(h0, h1);
            smu[U_H1L + arow * 68 + jc]       = packbf(v0 - h0, v1 - h1);
            smu[U_H1H + (arow + 8) * 68 + jc] = packbf(h2, h3);
            smu[U_H1L + (arow + 8) * 68 + jc] = packbf(v2 - h2, v3 - h3);
        }
        __syncthreads();

        // ============ GEMM2: D2 = h1 @ W2 + b2 (8 k16-steps) ============
        #pragma unroll
        for (int f = 0; f < 8; f++) {
            const float2 bv = *reinterpret_cast<const float2*>(
                sm + F_B2 + jw + f * 8 + tg * 2);
            d[f][0] = bv.x; d[f][1] = bv.y;
            d[f][2] = bv.x; d[f][3] = bv.y;
        }
        #pragma unroll 1
        for (int s = 0; s < 8; s++) {
            const int acol = s * 8 + tg;
            uint32_t ah[4], al[4];
            ah[0] = smu[U_H1H + arow * 68 + acol];
            ah[1] = smu[U_H1H + (arow + 8) * 68 + acol];
            ah[2] = smu[U_H1H + arow * 68 + acol + 4];
            ah[3] = smu[U_H1H + (arow + 8) * 68 + acol + 4];
            al[0] = smu[U_H1L + arow * 68 + acol];
            al[1] = smu[U_H1L + (arow + 8) * 68 + acol];
            al[2] = smu[U_H1L + arow * 68 + acol + 4];
            al[3] = smu[U_H1L + (arow + 8) * 68 + acol + 4];
            const int fb = ((s * 16 + ch * 8) * 32 + lane) * 2;
            #pragma unroll
            for (int f = 0; f < 8; f++) {
                const uint2 wh = *reinterpret_cast<const uint2*>(
                    smu + U_W2FH + fb + f * 64);
                const uint2 wl = *reinterpret_cast<const uint2*>(
                    smu + U_W2FL + fb + f * 64);
                mmab(d[f], ah, wh.x, wh.y);
                mmab(d[f], al, wh.x, wh.y);
                mmab(d[f], ah, wl.x, wl.y);
            }
        }

        // ============ epilogue: relu + W3 dot + reduce ============
        {
            float slo = 0.0f, shi = 0.0f;
            #pragma unroll
            for (int f = 0; f < 8; f++) {
                const int jc = jw + f * 8 + tg * 2;
                const float w3a = sm[F_W3 + jc];
                const float w3b = sm[F_W3 + jc + 1];
                slo = fmaf(fmaxf(d[f][0], 0.0f), w3a, slo);
                slo = fmaf(fmaxf(d[f][1], 0.0f), w3b, slo);
                shi = fmaf(fmaxf(d[f][2], 0.0f), w3a, shi);
                shi = fmaf(fmaxf(d[f][3], 0.0f), w3b, shi);
            }
            slo += __shfl_xor_sync(0xFFFFFFFF, slo, 1);
            slo += __shfl_xor_sync(0xFFFFFFFF, slo, 2);
            shi += __shfl_xor_sync(0xFFFFFFFF, shi, 1);
            shi += __shfl_xor_sync(0xFFFFFFFF, shi, 2);
            if (tg == 0) {
                sm[F_PART + arow * 2 + ch]       = slo;
                sm[F_PART + (arow + 8) * 2 + ch] = shi;
            }
        }
        __syncthreads();

        if (tid < 128)
            out[t * 128 + tid] = sm[F_PART + tid * 2]
                               + sm[F_PART + tid * 2 + 1]
                               + sm[F_B3];
        // next-iter feat write is fenced by the gather-phase __syncthreads
    }
}

extern "C" void kernel_launch(void* const* d_in, const int* in_sizes, int n_in,
                              void* d_out, int out_size)
{
    const float* x     = (const float*)d_in[0];
    const float* grids = (const float*)d_in[1];
    const float* W1    = (const float*)d_in[2];
    const float* b1    = (const float*)d_in[3];
    const float* W2    = (const float*)d_in[4];
    const float* b2    = (const float*)d_in[5];
    const float* W3    = (const float*)d_in[6];
    const float* b3    = (const float*)d_in[7];
    float* out = (float*)d_out;
    (void)in_sizes; (void)n_in; (void)out_size;

    cudaFuncSetAttribute(Model_61065845014888_kernel,
                         cudaFuncAttributeMaxDynamicSharedMemorySize, SMEM_BYTES);

    repack_kernel<<<(16 * GC + 255) / 256, 256>>>(grids);
    Model_61065845014888_kernel<<<NCTA, TPB, SMEM_BYTES>>>(
        x, W1, b1, W2, b2, W3, b3, out);
}